// round 4
// baseline (speedup 1.0000x reference)
#include <cuda_runtime.h>
#include <cuda_bf16.h>
#include <cstdint>

// Problem dims (fixed per reference setup_inputs)
#define MDIM 8192
#define KDIM 2048
#define KCAT 4096   // [hi | lo] concatenated along K
#define NDIM 2048

// Scratch: bf16 split-x and duplicated binarized W (no allocations allowed)
__device__ __nv_bfloat16 g_xcat[(size_t)MDIM * KCAT];   // 64 MB
__device__ __nv_bfloat16 g_wcat[(size_t)NDIM * KCAT];   // 16 MB

// ---------------------------------------------------------------------------
// Prep kernels
// ---------------------------------------------------------------------------

// Binarize weights to {+1,-1} bf16, duplicated into both K halves of Wcat.
__global__ void prep_w_kernel(const float* __restrict__ w) {
    int idx = blockIdx.x * blockDim.x + threadIdx.x;          // over NDIM*KDIM/4
    if (idx >= NDIM * KDIM / 4) return;
    const float4 w4 = reinterpret_cast<const float4*>(w)[idx];
    int e = idx * 4;
    int o = e / KDIM;
    int k = e % KDIM;

    __nv_bfloat16 b0 = __float2bfloat16(w4.x >= 0.f ? 1.f : -1.f);
    __nv_bfloat16 b1 = __float2bfloat16(w4.y >= 0.f ? 1.f : -1.f);
    __nv_bfloat16 b2 = __float2bfloat16(w4.z >= 0.f ? 1.f : -1.f);
    __nv_bfloat16 b3 = __float2bfloat16(w4.w >= 0.f ? 1.f : -1.f);

    __nv_bfloat162 p0 = __halves2bfloat162(b0, b1);
    __nv_bfloat162 p1 = __halves2bfloat162(b2, b3);

    __nv_bfloat162* dst0 = reinterpret_cast<__nv_bfloat162*>(&g_wcat[(size_t)o * KCAT + k]);
    __nv_bfloat162* dst1 = reinterpret_cast<__nv_bfloat162*>(&g_wcat[(size_t)o * KCAT + k + KDIM]);
    dst0[0] = p0; dst0[1] = p1;
    dst1[0] = p0; dst1[1] = p1;
}

// Split x into bf16 hi + bf16 lo (x ~= hi + lo), hi in first K half, lo in second.
__global__ void prep_x_kernel(const float* __restrict__ x) {
    int idx = blockIdx.x * blockDim.x + threadIdx.x;          // over MDIM*KDIM/4
    if (idx >= MDIM * KDIM / 4) return;
    const float4 v4 = reinterpret_cast<const float4*>(x)[idx];
    int e = idx * 4;
    int m = e / KDIM;
    int k = e % KDIM;

    float v[4] = {v4.x, v4.y, v4.z, v4.w};
    __nv_bfloat16 hi[4], lo[4];
#pragma unroll
    for (int i = 0; i < 4; i++) {
        hi[i] = __float2bfloat16(v[i]);
        lo[i] = __float2bfloat16(v[i] - __bfloat162float(hi[i]));
    }

    __nv_bfloat162* dhi = reinterpret_cast<__nv_bfloat162*>(&g_xcat[(size_t)m * KCAT + k]);
    __nv_bfloat162* dlo = reinterpret_cast<__nv_bfloat162*>(&g_xcat[(size_t)m * KCAT + k + KDIM]);
    dhi[0] = __halves2bfloat162(hi[0], hi[1]);
    dhi[1] = __halves2bfloat162(hi[2], hi[3]);
    dlo[0] = __halves2bfloat162(lo[0], lo[1]);
    dlo[1] = __halves2bfloat162(lo[2], lo[3]);
}

// ---------------------------------------------------------------------------
// GEMM: out[M,N] = xcat[M,KCAT] @ wcat[N,KCAT]^T + bias
// 128x128x32 CTA tile, 8 warps (4 along M x 2 along N), warp tile 32x64,
// mma.sync.m16n8k16 bf16 -> f32, cp.async double-buffered smem.
// ---------------------------------------------------------------------------

#define BM 128
#define BN 128
#define BK 32
#define SSTR 40   // smem row stride in bf16 elems (32 + 8 pad -> conflict-free ldmatrix)

__device__ __forceinline__ void cp_async16(void* smem_dst, const void* gmem_src) {
    uint32_t s = (uint32_t)__cvta_generic_to_shared(smem_dst);
    asm volatile("cp.async.cg.shared.global [%0], [%1], 16;\n" :: "r"(s), "l"(gmem_src));
}
__device__ __forceinline__ void cp_async_commit() {
    asm volatile("cp.async.commit_group;\n");
}
__device__ __forceinline__ void cp_async_wait_all() {
    asm volatile("cp.async.wait_group 0;\n");
}

__device__ __forceinline__ void ldmatrix_x4(uint32_t& r0, uint32_t& r1, uint32_t& r2, uint32_t& r3,
                                            const __nv_bfloat16* p) {
    uint32_t a = (uint32_t)__cvta_generic_to_shared(p);
    asm volatile("ldmatrix.sync.aligned.m8n8.x4.shared.b16 {%0,%1,%2,%3}, [%4];\n"
                 : "=r"(r0), "=r"(r1), "=r"(r2), "=r"(r3) : "r"(a));
}

__device__ __forceinline__ void mma_16816(float c[4], const uint32_t a[4], const uint32_t b[2]) {
    asm volatile(
        "mma.sync.aligned.m16n8k16.row.col.f32.bf16.bf16.f32 "
        "{%0,%1,%2,%3}, {%4,%5,%6,%7}, {%8,%9}, {%0,%1,%2,%3};\n"
        : "+f"(c[0]), "+f"(c[1]), "+f"(c[2]), "+f"(c[3])
        : "r"(a[0]), "r"(a[1]), "r"(a[2]), "r"(a[3]), "r"(b[0]), "r"(b[1]));
}

__global__ void __launch_bounds__(256)
gemm_kernel(const float* __restrict__ bias, float* __restrict__ out) {
    __shared__ __align__(128) __nv_bfloat16 sA[2][BM * SSTR];
    __shared__ __align__(128) __nv_bfloat16 sB[2][BN * SSTR];

    const int tid  = threadIdx.x;
    const int bm   = blockIdx.y;      // M tile: 0..63
    const int bn   = blockIdx.x;      // N tile: 0..15
    const int warp = tid >> 5;
    const int lane = tid & 31;
    const int wm   = warp & 3;        // 4 warps along M
    const int wn   = warp >> 2;       // 2 warps along N

    // Global->shared loader mapping: per tile, 128 rows x 4 chunks(16B), 512 units, 2/thread
    const int ld_row0   = tid >> 2;          // 0..63
    const int ld_chunk  = tid & 3;           // 0..3
    const size_t a_gbase = (size_t)(bm * BM) * KCAT;
    const size_t b_gbase = (size_t)(bn * BN) * KCAT;

    const int KT = KCAT / BK;   // 128 k-tiles

    auto load_tile = [&](int stage, int kt) {
        int kc = kt * BK + ld_chunk * 8;
#pragma unroll
        for (int i = 0; i < 2; i++) {
            int row = ld_row0 + i * 64;
            cp_async16(&sA[stage][row * SSTR + ld_chunk * 8],
                       &g_xcat[a_gbase + (size_t)row * KCAT + kc]);
            cp_async16(&sB[stage][row * SSTR + ld_chunk * 8],
                       &g_wcat[b_gbase + (size_t)row * KCAT + kc]);
        }
    };

    float acc[2][8][4];
#pragma unroll
    for (int mi = 0; mi < 2; mi++)
#pragma unroll
        for (int ni = 0; ni < 8; ni++)
#pragma unroll
            for (int r = 0; r < 4; r++) acc[mi][ni][r] = 0.f;

    // Prologue
    load_tile(0, 0);
    cp_async_commit();

    for (int kt = 0; kt < KT; kt++) {
        cp_async_wait_all();
        __syncthreads();

        if (kt + 1 < KT) {
            load_tile((kt + 1) & 1, kt + 1);
            cp_async_commit();
        }

        const __nv_bfloat16* As = sA[kt & 1];
        const __nv_bfloat16* Bs = sB[kt & 1];

#pragma unroll
        for (int ks = 0; ks < 2; ks++) {
            const int kofs = ks * 16 + (lane >> 4) * 8;

            uint32_t af[2][4];
#pragma unroll
            for (int mi = 0; mi < 2; mi++) {
                int row = wm * 32 + mi * 16 + (lane & 15);
                ldmatrix_x4(af[mi][0], af[mi][1], af[mi][2], af[mi][3],
                            &As[row * SSTR + kofs]);
            }

            uint32_t bf[8][2];
#pragma unroll
            for (int ng = 0; ng < 4; ng++) {
                int nrow = wn * 64 + ng * 16 + (lane & 15);
                uint32_t r0, r1, r2, r3;
                ldmatrix_x4(r0, r1, r2, r3, &Bs[nrow * SSTR + kofs]);
                bf[ng * 2 + 0][0] = r0; bf[ng * 2 + 0][1] = r2;
                bf[ng * 2 + 1][0] = r1; bf[ng * 2 + 1][1] = r3;
            }

#pragma unroll
            for (int mi = 0; mi < 2; mi++)
#pragma unroll
                for (int ni = 0; ni < 8; ni++)
                    mma_16816(acc[mi][ni], af[mi], bf[ni]);
        }
        __syncthreads();
    }

    // Epilogue: c layout for m16n8: lane/4 -> row (regs 2,3 add +8), (lane%4)*2 -> col
    const int grow = lane >> 2;
    const int gcol = (lane & 3) * 2;
#pragma unroll
    for (int mi = 0; mi < 2; mi++) {
#pragma unroll
        for (int ni = 0; ni < 8; ni++) {
            int row = bm * BM + wm * 32 + mi * 16 + grow;
            int col = bn * BN + wn * 64 + ni * 8 + gcol;
            float b0 = bias[col];
            float b1 = bias[col + 1];
            float2 v0 = make_float2(acc[mi][ni][0] + b0, acc[mi][ni][1] + b1);
            float2 v1 = make_float2(acc[mi][ni][2] + b0, acc[mi][ni][3] + b1);
            *reinterpret_cast<float2*>(&out[(size_t)row * NDIM + col]) = v0;
            *reinterpret_cast<float2*>(&out[(size_t)(row + 8) * NDIM + col]) = v1;
        }
    }
}

// ---------------------------------------------------------------------------
// Launch
// ---------------------------------------------------------------------------
extern "C" void kernel_launch(void* const* d_in, const int* in_sizes, int n_in,
                              void* d_out, int out_size) {
    const float* x    = (const float*)d_in[0];
    const float* w    = (const float*)d_in[1];
    const float* bias = (const float*)d_in[2];
    float* out        = (float*)d_out;

    {
        int n = NDIM * KDIM / 4;
        prep_w_kernel<<<(n + 255) / 256, 256>>>(w);
    }
    {
        int n = MDIM * KDIM / 4;
        prep_x_kernel<<<(n + 255) / 256, 256>>>(x);
    }
    {
        dim3 grid(NDIM / BN, MDIM / BM);   // (16, 64)
        gemm_kernel<<<grid, 256>>>(bias, out);
    }
}

// round 6
// speedup vs baseline: 1.7328x; 1.7328x over previous
#include <cuda_runtime.h>
#include <cuda_fp16.h>
#include <cstdint>

// Problem dims
#define MDIM 8192
#define KDIM 2048
#define NDIM 2048

// Scratch (no allocations allowed)
__device__ __half g_xh[(size_t)MDIM * KDIM];   // 32 MB
__device__ __half g_wh[(size_t)NDIM * KDIM];   // 8 MB

// ---------------------------------------------------------------------------
// Prep: fp16 convert (16B stores)
// ---------------------------------------------------------------------------
__global__ void prep_w_kernel(const float* __restrict__ w) {
    int idx = blockIdx.x * blockDim.x + threadIdx.x;    // over NDIM*KDIM/8
    if (idx >= NDIM * KDIM / 8) return;
    const float4* src = reinterpret_cast<const float4*>(w) + idx * 2;
    float4 a = src[0], b = src[1];
    __half2 h[4];
    h[0] = __halves2half2(__float2half(a.x >= 0.f ? 1.f : -1.f),
                          __float2half(a.y >= 0.f ? 1.f : -1.f));
    h[1] = __halves2half2(__float2half(a.z >= 0.f ? 1.f : -1.f),
                          __float2half(a.w >= 0.f ? 1.f : -1.f));
    h[2] = __halves2half2(__float2half(b.x >= 0.f ? 1.f : -1.f),
                          __float2half(b.y >= 0.f ? 1.f : -1.f));
    h[3] = __halves2half2(__float2half(b.z >= 0.f ? 1.f : -1.f),
                          __float2half(b.w >= 0.f ? 1.f : -1.f));
    reinterpret_cast<uint4*>(g_wh)[idx] = *reinterpret_cast<uint4*>(h);
}

__global__ void prep_x_kernel(const float* __restrict__ x) {
    int idx = blockIdx.x * blockDim.x + threadIdx.x;    // over MDIM*KDIM/8
    if (idx >= MDIM * KDIM / 8) return;
    const float4* src = reinterpret_cast<const float4*>(x) + idx * 2;
    float4 a = src[0], b = src[1];
    __half2 h[4];
    h[0] = __floats2half2_rn(a.x, a.y);
    h[1] = __floats2half2_rn(a.z, a.w);
    h[2] = __floats2half2_rn(b.x, b.y);
    h[3] = __floats2half2_rn(b.z, b.w);
    reinterpret_cast<uint4*>(g_xh)[idx] = *reinterpret_cast<uint4*>(h);
}

// ---------------------------------------------------------------------------
// GEMM: out[M,N] = xh[M,K] @ wh[N,K]^T + bias
// CTA 128x256x32, 8 warps (4 M x 2 N), warp tile 32x128,
// mma.sync.m16n8k16 f16->f32, 3-stage cp.async pipeline.
// ---------------------------------------------------------------------------
#define BM 128
#define BN 256
#define BK 32
#define STAGES 3
#define KT (KDIM / BK)          // 64
#define SSTR 40                 // smem row stride in halfs (32 + 8 pad)
#define A_ROWS BM
#define B_ROWS BN
#define STAGE_HALFS ((A_ROWS + B_ROWS) * SSTR)          // 15360 halfs
#define STAGE_BYTES (STAGE_HALFS * 2)                    // 30720 B
#define SMEM_BYTES (STAGES * STAGE_BYTES)                // 92160 B

__device__ __forceinline__ void cp_async16(void* smem_dst, const void* gmem_src) {
    uint32_t s = (uint32_t)__cvta_generic_to_shared(smem_dst);
    asm volatile("cp.async.cg.shared.global [%0], [%1], 16;\n" :: "r"(s), "l"(gmem_src));
}
#define CP_COMMIT() asm volatile("cp.async.commit_group;\n" ::: "memory")

__device__ __forceinline__ void ldmatrix_x4(uint32_t& r0, uint32_t& r1, uint32_t& r2, uint32_t& r3,
                                            const __half* p) {
    uint32_t a = (uint32_t)__cvta_generic_to_shared(p);
    asm volatile("ldmatrix.sync.aligned.m8n8.x4.shared.b16 {%0,%1,%2,%3}, [%4];\n"
                 : "=r"(r0), "=r"(r1), "=r"(r2), "=r"(r3) : "r"(a));
}

__device__ __forceinline__ void mma_16816(float c[4], const uint32_t a[4], const uint32_t b[2]) {
    asm volatile(
        "mma.sync.aligned.m16n8k16.row.col.f32.f16.f16.f32 "
        "{%0,%1,%2,%3}, {%4,%5,%6,%7}, {%8,%9}, {%0,%1,%2,%3};\n"
        : "+f"(c[0]), "+f"(c[1]), "+f"(c[2]), "+f"(c[3])
        : "r"(a[0]), "r"(a[1]), "r"(a[2]), "r"(a[3]), "r"(b[0]), "r"(b[1]));
}

extern __shared__ __align__(128) char dynsmem[];

__global__ void __launch_bounds__(256, 1)
gemm_kernel(const float* __restrict__ bias, float* __restrict__ out) {
    const int tid  = threadIdx.x;
    const int warp = tid >> 5;
    const int lane = tid & 31;
    const int bn   = blockIdx.x;      // 0..7
    const int bm   = blockIdx.y;      // 0..63
    const int wm   = warp & 3;        // 4 warps along M
    const int wn   = warp >> 2;       // 2 warps along N

    const __half* gA = g_xh + (size_t)(bm * BM) * KDIM;
    const __half* gB = g_wh + (size_t)(bn * BN) * KDIM;

    // Loader: per stage, rows have 4 x 16B chunks (32 halfs). A: 512 chunks, B: 1024.
    auto load_stage = [&](int stage, int kt) {
        __half* sA = reinterpret_cast<__half*>(dynsmem + stage * STAGE_BYTES);
        __half* sB = sA + A_ROWS * SSTR;
        const int kb = kt * BK;
#pragma unroll
        for (int t = 0; t < 2; t++) {              // A
            int ch = tid + t * 256;                // 0..511
            int row = ch >> 2, c = ch & 3;
            cp_async16(&sA[row * SSTR + c * 8], gA + (size_t)row * KDIM + kb + c * 8);
        }
#pragma unroll
        for (int t = 0; t < 4; t++) {              // B
            int ch = tid + t * 256;                // 0..1023
            int row = ch >> 2, c = ch & 3;
            cp_async16(&sB[row * SSTR + c * 8], gB + (size_t)row * KDIM + kb + c * 8);
        }
    };

    float acc[2][16][4];
#pragma unroll
    for (int mi = 0; mi < 2; mi++)
#pragma unroll
        for (int ni = 0; ni < 16; ni++)
#pragma unroll
            for (int r = 0; r < 4; r++) acc[mi][ni][r] = 0.f;

    // Prologue: stages 0,1
    load_stage(0, 0); CP_COMMIT();
    load_stage(1, 1); CP_COMMIT();

    for (int i = 0; i < KT; i++) {
        const int s = i % STAGES;
        if (i < KT - 1) asm volatile("cp.async.wait_group 1;\n" ::: "memory");
        else            asm volatile("cp.async.wait_group 0;\n" ::: "memory");
        __syncthreads();

        if (i + 2 < KT) {
            load_stage((i + 2) % STAGES, i + 2);
            CP_COMMIT();
        }

        const __half* As = reinterpret_cast<const __half*>(dynsmem + s * STAGE_BYTES);
        const __half* Bs = As + A_ROWS * SSTR;

#pragma unroll
        for (int ks = 0; ks < 2; ks++) {
            const int kofs = ks * 16 + (lane >> 4) * 8;

            uint32_t af[2][4];
#pragma unroll
            for (int mi = 0; mi < 2; mi++) {
                int row = wm * 32 + mi * 16 + (lane & 15);
                ldmatrix_x4(af[mi][0], af[mi][1], af[mi][2], af[mi][3],
                            &As[row * SSTR + kofs]);
            }

            uint32_t bf[16][2];
#pragma unroll
            for (int ng = 0; ng < 8; ng++) {
                int nrow = wn * 128 + ng * 16 + (lane & 15);
                uint32_t r0, r1, r2, r3;
                ldmatrix_x4(r0, r1, r2, r3, &Bs[nrow * SSTR + kofs]);
                bf[ng * 2 + 0][0] = r0; bf[ng * 2 + 0][1] = r2;
                bf[ng * 2 + 1][0] = r1; bf[ng * 2 + 1][1] = r3;
            }

#pragma unroll
            for (int mi = 0; mi < 2; mi++)
#pragma unroll
                for (int ni = 0; ni < 16; ni++)
                    mma_16816(acc[mi][ni], af[mi], bf[ni]);
        }
        __syncthreads();
    }

    // Epilogue: m16n8 frag: row = lane>>2 (+8 for regs 2,3), col = (lane&3)*2
    const int grow = lane >> 2;
    const int gcol = (lane & 3) * 2;
#pragma unroll
    for (int mi = 0; mi < 2; mi++) {
#pragma unroll
        for (int ni = 0; ni < 16; ni++) {
            int row = bm * BM + wm * 32 + mi * 16 + grow;
            int col = bn * BN + wn * 128 + ni * 8 + gcol;
            float b0 = __ldg(&bias[col]);
            float b1 = __ldg(&bias[col + 1]);
            float2 v0 = make_float2(acc[mi][ni][0] + b0, acc[mi][ni][1] + b1);
            float2 v1 = make_float2(acc[mi][ni][2] + b0, acc[mi][ni][3] + b1);
            *reinterpret_cast<float2*>(&out[(size_t)row * NDIM + col]) = v0;
            *reinterpret_cast<float2*>(&out[(size_t)(row + 8) * NDIM + col]) = v1;
        }
    }
}

// ---------------------------------------------------------------------------
// Launch
// ---------------------------------------------------------------------------
extern "C" void kernel_launch(void* const* d_in, const int* in_sizes, int n_in,
                              void* d_out, int out_size) {
    const float* x    = (const float*)d_in[0];
    const float* w    = (const float*)d_in[1];
    const float* bias = (const float*)d_in[2];
    float* out        = (float*)d_out;

    {
        int n = NDIM * KDIM / 8;
        prep_w_kernel<<<(n + 255) / 256, 256>>>(w);
    }
    {
        int n = MDIM * KDIM / 8;
        prep_x_kernel<<<(n + 255) / 256, 256>>>(x);
    }
    {
        cudaFuncSetAttribute(gemm_kernel,
                             cudaFuncAttributeMaxDynamicSharedMemorySize, SMEM_BYTES);
        dim3 grid(NDIM / BN, MDIM / BM);   // (8, 64)
        gemm_kernel<<<grid, 256, SMEM_BYTES>>>(bias, out);
    }
}

// round 7
// speedup vs baseline: 1.9535x; 1.1274x over previous
#include <cuda_runtime.h>
#include <cuda_fp16.h>
#include <cstdint>

// Problem dims
#define MDIM 8192
#define KDIM 2048
#define NDIM 2048

// Scratch (no allocations allowed)
__device__ __half g_xh[(size_t)MDIM * KDIM];   // 32 MB
__device__ __half g_wh[(size_t)NDIM * KDIM];   // 8 MB

// ---------------------------------------------------------------------------
// Prep: fp16 convert (16B stores)
// ---------------------------------------------------------------------------
__global__ void prep_w_kernel(const float* __restrict__ w) {
    int idx = blockIdx.x * blockDim.x + threadIdx.x;    // over NDIM*KDIM/8
    if (idx >= NDIM * KDIM / 8) return;
    const float4* src = reinterpret_cast<const float4*>(w) + idx * 2;
    float4 a = src[0], b = src[1];
    __half2 h[4];
    h[0] = __halves2half2(__float2half(a.x >= 0.f ? 1.f : -1.f),
                          __float2half(a.y >= 0.f ? 1.f : -1.f));
    h[1] = __halves2half2(__float2half(a.z >= 0.f ? 1.f : -1.f),
                          __float2half(a.w >= 0.f ? 1.f : -1.f));
    h[2] = __halves2half2(__float2half(b.x >= 0.f ? 1.f : -1.f),
                          __float2half(b.y >= 0.f ? 1.f : -1.f));
    h[3] = __halves2half2(__float2half(b.z >= 0.f ? 1.f : -1.f),
                          __float2half(b.w >= 0.f ? 1.f : -1.f));
    reinterpret_cast<uint4*>(g_wh)[idx] = *reinterpret_cast<uint4*>(h);
}

__global__ void prep_x_kernel(const float* __restrict__ x) {
    int idx = blockIdx.x * blockDim.x + threadIdx.x;    // over MDIM*KDIM/8
    if (idx >= MDIM * KDIM / 8) return;
    const float4* src = reinterpret_cast<const float4*>(x) + idx * 2;
    float4 a = src[0], b = src[1];
    __half2 h[4];
    h[0] = __floats2half2_rn(a.x, a.y);
    h[1] = __floats2half2_rn(a.z, a.w);
    h[2] = __floats2half2_rn(b.x, b.y);
    h[3] = __floats2half2_rn(b.z, b.w);
    reinterpret_cast<uint4*>(g_xh)[idx] = *reinterpret_cast<uint4*>(h);
}

// ---------------------------------------------------------------------------
// GEMM: out[M,N] = xh[M,K] @ wh[N,K]^T + bias
// CTA 128x128x32, 8 warps (4 M x 2 N), warp tile 32x64,
// mma.sync.m16n8k16 f16->f32, 3-stage cp.async pipeline, 2 CTAs/SM.
// ---------------------------------------------------------------------------
#define BM 128
#define BN 128
#define BK 32
#define STAGES 3
#define KT (KDIM / BK)          // 64
#define SSTR 40                 // smem row stride in halfs (32 + 8 pad)
#define STAGE_HALFS ((BM + BN) * SSTR)                   // 10240 halfs
#define STAGE_BYTES (STAGE_HALFS * 2)                    // 20480 B
#define SMEM_BYTES (STAGES * STAGE_BYTES)                // 61440 B

__device__ __forceinline__ void cp_async16(void* smem_dst, const void* gmem_src) {
    uint32_t s = (uint32_t)__cvta_generic_to_shared(smem_dst);
    asm volatile("cp.async.cg.shared.global [%0], [%1], 16;\n" :: "r"(s), "l"(gmem_src));
}
#define CP_COMMIT() asm volatile("cp.async.commit_group;\n" ::: "memory")

__device__ __forceinline__ void ldmatrix_x4(uint32_t& r0, uint32_t& r1, uint32_t& r2, uint32_t& r3,
                                            const __half* p) {
    uint32_t a = (uint32_t)__cvta_generic_to_shared(p);
    asm volatile("ldmatrix.sync.aligned.m8n8.x4.shared.b16 {%0,%1,%2,%3}, [%4];\n"
                 : "=r"(r0), "=r"(r1), "=r"(r2), "=r"(r3) : "r"(a));
}

__device__ __forceinline__ void mma_16816(float c[4], const uint32_t a[4], const uint32_t b[2]) {
    asm volatile(
        "mma.sync.aligned.m16n8k16.row.col.f32.f16.f16.f32 "
        "{%0,%1,%2,%3}, {%4,%5,%6,%7}, {%8,%9}, {%0,%1,%2,%3};\n"
        : "+f"(c[0]), "+f"(c[1]), "+f"(c[2]), "+f"(c[3])
        : "r"(a[0]), "r"(a[1]), "r"(a[2]), "r"(a[3]), "r"(b[0]), "r"(b[1]));
}

extern __shared__ __align__(128) char dynsmem[];

__global__ void __launch_bounds__(256, 2)
gemm_kernel(const float* __restrict__ bias, float* __restrict__ out) {
    const int tid  = threadIdx.x;
    const int warp = tid >> 5;
    const int lane = tid & 31;
    const int bn   = blockIdx.x;      // 0..15
    const int bm   = blockIdx.y;      // 0..63
    const int wm   = warp & 3;        // 4 warps along M
    const int wn   = warp >> 2;       // 2 warps along N

    const __half* gA = g_xh + (size_t)(bm * BM) * KDIM;
    const __half* gB = g_wh + (size_t)(bn * BN) * KDIM;

    // Loader: per stage, each of 256 rows (A then B) has 4 x 16B chunks -> 1024
    // chunks, 4 per thread.
    auto load_stage = [&](int stage, int kt) {
        __half* sA = reinterpret_cast<__half*>(dynsmem + stage * STAGE_BYTES);
        __half* sB = sA + BM * SSTR;
        const int kb = kt * BK;
#pragma unroll
        for (int t = 0; t < 2; t++) {              // A: 512 chunks
            int ch = tid + t * 256;
            int row = ch >> 2, c = ch & 3;
            cp_async16(&sA[row * SSTR + c * 8], gA + (size_t)row * KDIM + kb + c * 8);
        }
#pragma unroll
        for (int t = 0; t < 2; t++) {              // B: 512 chunks
            int ch = tid + t * 256;
            int row = ch >> 2, c = ch & 3;
            cp_async16(&sB[row * SSTR + c * 8], gB + (size_t)row * KDIM + kb + c * 8);
        }
    };

    float acc[2][8][4];
#pragma unroll
    for (int mi = 0; mi < 2; mi++)
#pragma unroll
        for (int ni = 0; ni < 8; ni++)
#pragma unroll
            for (int r = 0; r < 4; r++) acc[mi][ni][r] = 0.f;

    // Prologue: stages 0,1
    load_stage(0, 0); CP_COMMIT();
    load_stage(1, 1); CP_COMMIT();

    for (int i = 0; i < KT; i++) {
        const int s = i % STAGES;
        if (i < KT - 1) asm volatile("cp.async.wait_group 1;\n" ::: "memory");
        else            asm volatile("cp.async.wait_group 0;\n" ::: "memory");
        __syncthreads();

        if (i + 2 < KT) {
            load_stage((i + 2) % STAGES, i + 2);
            CP_COMMIT();
        }

        const __half* As = reinterpret_cast<const __half*>(dynsmem + s * STAGE_BYTES);
        const __half* Bs = As + BM * SSTR;

#pragma unroll
        for (int ks = 0; ks < 2; ks++) {
            const int kofs = ks * 16 + (lane >> 4) * 8;

            uint32_t af[2][4];
#pragma unroll
            for (int mi = 0; mi < 2; mi++) {
                int row = wm * 32 + mi * 16 + (lane & 15);
                ldmatrix_x4(af[mi][0], af[mi][1], af[mi][2], af[mi][3],
                            &As[row * SSTR + kofs]);
            }

            uint32_t bf[8][2];
#pragma unroll
            for (int ng = 0; ng < 4; ng++) {
                int nrow = wn * 64 + ng * 16 + (lane & 15);
                uint32_t r0, r1, r2, r3;
                ldmatrix_x4(r0, r1, r2, r3, &Bs[nrow * SSTR + kofs]);
                bf[ng * 2 + 0][0] = r0; bf[ng * 2 + 0][1] = r2;
                bf[ng * 2 + 1][0] = r1; bf[ng * 2 + 1][1] = r3;
            }

#pragma unroll
            for (int mi = 0; mi < 2; mi++)
#pragma unroll
                for (int ni = 0; ni < 8; ni++)
                    mma_16816(acc[mi][ni], af[mi], bf[ni]);
        }
        __syncthreads();
    }

    // Epilogue: m16n8 frag: row = lane>>2 (+8 for regs 2,3), col = (lane&3)*2
    const int grow = lane >> 2;
    const int gcol = (lane & 3) * 2;
#pragma unroll
    for (int mi = 0; mi < 2; mi++) {
#pragma unroll
        for (int ni = 0; ni < 8; ni++) {
            int row = bm * BM + wm * 32 + mi * 16 + grow;
            int col = bn * BN + wn * 64 + ni * 8 + gcol;
            float b0 = __ldg(&bias[col]);
            float b1 = __ldg(&bias[col + 1]);
            float2 v0 = make_float2(acc[mi][ni][0] + b0, acc[mi][ni][1] + b1);
            float2 v1 = make_float2(acc[mi][ni][2] + b0, acc[mi][ni][3] + b1);
            *reinterpret_cast<float2*>(&out[(size_t)row * NDIM + col]) = v0;
            *reinterpret_cast<float2*>(&out[(size_t)(row + 8) * NDIM + col]) = v1;
        }
    }
}

// ---------------------------------------------------------------------------
// Launch
// ---------------------------------------------------------------------------
extern "C" void kernel_launch(void* const* d_in, const int* in_sizes, int n_in,
                              void* d_out, int out_size) {
    const float* x    = (const float*)d_in[0];
    const float* w    = (const float*)d_in[1];
    const float* bias = (const float*)d_in[2];
    float* out        = (float*)d_out;

    {
        int n = NDIM * KDIM / 8;
        prep_w_kernel<<<(n + 255) / 256, 256>>>(w);
    }
    {
        int n = MDIM * KDIM / 8;
        prep_x_kernel<<<(n + 255) / 256, 256>>>(x);
    }
    {
        cudaFuncSetAttribute(gemm_kernel,
                             cudaFuncAttributeMaxDynamicSharedMemorySize, SMEM_BYTES);
        dim3 grid(NDIM / BN, MDIM / BM);   // (16, 64)
        gemm_kernel<<<grid, 256, SMEM_BYTES>>>(bias, out);
    }
}

// round 8
// speedup vs baseline: 2.2456x; 1.1495x over previous
#include <cuda_runtime.h>
#include <cuda_fp16.h>
#include <cstdint>

// Problem dims
#define MDIM 8192
#define KDIM 2048
#define NDIM 2048

// Scratch (no allocations allowed)
__device__ __half g_xh[(size_t)MDIM * KDIM];   // 32 MB
__device__ __half g_wh[(size_t)NDIM * KDIM];   // 8 MB

// ---------------------------------------------------------------------------
// Merged prep: first NW threads binarize W, rest convert x. 16B stores.
// ---------------------------------------------------------------------------
#define NW (NDIM * KDIM / 8)
#define NX (MDIM * KDIM / 8)

__global__ void prep_kernel(const float* __restrict__ w, const float* __restrict__ x) {
    int idx = blockIdx.x * blockDim.x + threadIdx.x;
    if (idx < NW) {
        const float4* src = reinterpret_cast<const float4*>(w) + idx * 2;
        float4 a = src[0], b = src[1];
        __half2 h[4];
        h[0] = __halves2half2(__float2half(a.x >= 0.f ? 1.f : -1.f),
                              __float2half(a.y >= 0.f ? 1.f : -1.f));
        h[1] = __halves2half2(__float2half(a.z >= 0.f ? 1.f : -1.f),
                              __float2half(a.w >= 0.f ? 1.f : -1.f));
        h[2] = __halves2half2(__float2half(b.x >= 0.f ? 1.f : -1.f),
                              __float2half(b.y >= 0.f ? 1.f : -1.f));
        h[3] = __halves2half2(__float2half(b.z >= 0.f ? 1.f : -1.f),
                              __float2half(b.w >= 0.f ? 1.f : -1.f));
        reinterpret_cast<uint4*>(g_wh)[idx] = *reinterpret_cast<uint4*>(h);
    } else if (idx < NW + NX) {
        int xi = idx - NW;
        const float4* src = reinterpret_cast<const float4*>(x) + xi * 2;
        float4 a = src[0], b = src[1];
        __half2 h[4];
        h[0] = __floats2half2_rn(a.x, a.y);
        h[1] = __floats2half2_rn(a.z, a.w);
        h[2] = __floats2half2_rn(b.x, b.y);
        h[3] = __floats2half2_rn(b.z, b.w);
        reinterpret_cast<uint4*>(g_xh)[xi] = *reinterpret_cast<uint4*>(h);
    }
}

// ---------------------------------------------------------------------------
// GEMM: out[M,N] = xh[M,K] @ wh[N,K]^T + bias
// CTA 128x128x64, 8 warps (4 M x 2 N), warp tile 32x64,
// mma.sync.m16n8k16 f16->f32, 2-stage cp.async (BK=64), 2 CTAs/SM.
// ---------------------------------------------------------------------------
#define BM 128
#define BN 128
#define BK 64
#define KT (KDIM / BK)          // 32
#define SSTR 72                 // smem row stride in halfs (64 + 8 pad)
#define STAGE_HALFS ((BM + BN) * SSTR)                   // 18432 halfs
#define STAGE_BYTES (STAGE_HALFS * 2)                    // 36864 B
#define SMEM_BYTES (2 * STAGE_BYTES)                     // 73728 B

__device__ __forceinline__ void cp_async16(void* smem_dst, const void* gmem_src) {
    uint32_t s = (uint32_t)__cvta_generic_to_shared(smem_dst);
    asm volatile("cp.async.cg.shared.global [%0], [%1], 16;\n" :: "r"(s), "l"(gmem_src));
}
#define CP_COMMIT() asm volatile("cp.async.commit_group;\n" ::: "memory")

__device__ __forceinline__ void ldmatrix_x4(uint32_t& r0, uint32_t& r1, uint32_t& r2, uint32_t& r3,
                                            const __half* p) {
    uint32_t a = (uint32_t)__cvta_generic_to_shared(p);
    asm volatile("ldmatrix.sync.aligned.m8n8.x4.shared.b16 {%0,%1,%2,%3}, [%4];\n"
                 : "=r"(r0), "=r"(r1), "=r"(r2), "=r"(r3) : "r"(a));
}

__device__ __forceinline__ void mma_16816(float c[4], const uint32_t a[4], const uint32_t b[2]) {
    asm volatile(
        "mma.sync.aligned.m16n8k16.row.col.f32.f16.f16.f32 "
        "{%0,%1,%2,%3}, {%4,%5,%6,%7}, {%8,%9}, {%0,%1,%2,%3};\n"
        : "+f"(c[0]), "+f"(c[1]), "+f"(c[2]), "+f"(c[3])
        : "r"(a[0]), "r"(a[1]), "r"(a[2]), "r"(a[3]), "r"(b[0]), "r"(b[1]));
}

extern __shared__ __align__(128) char dynsmem[];

__global__ void __launch_bounds__(256, 2)
gemm_kernel(const float* __restrict__ bias, float* __restrict__ out) {
    const int tid  = threadIdx.x;
    const int warp = tid >> 5;
    const int lane = tid & 31;
    const int bn   = blockIdx.x;      // 0..15
    const int bm   = blockIdx.y;      // 0..63
    const int wm   = warp & 3;        // 4 warps along M
    const int wn   = warp >> 2;       // 2 warps along N

    const __half* gA = g_xh + (size_t)(bm * BM) * KDIM;
    const __half* gB = g_wh + (size_t)(bn * BN) * KDIM;

    // Loader: per stage, 256 rows (A then B) x 8 chunks of 16B = 2048 chunks,
    // 8 per thread.
    auto load_stage = [&](int stage, int kt) {
        __half* sA = reinterpret_cast<__half*>(dynsmem + stage * STAGE_BYTES);
        __half* sB = sA + BM * SSTR;
        const int kb = kt * BK;
#pragma unroll
        for (int t = 0; t < 4; t++) {              // A: 1024 chunks
            int ch = tid + t * 256;
            int row = ch >> 3, c = ch & 7;
            cp_async16(&sA[row * SSTR + c * 8], gA + (size_t)row * KDIM + kb + c * 8);
        }
#pragma unroll
        for (int t = 0; t < 4; t++) {              // B: 1024 chunks
            int ch = tid + t * 256;
            int row = ch >> 3, c = ch & 7;
            cp_async16(&sB[row * SSTR + c * 8], gB + (size_t)row * KDIM + kb + c * 8);
        }
    };

    float acc[2][8][4];
#pragma unroll
    for (int mi = 0; mi < 2; mi++)
#pragma unroll
        for (int ni = 0; ni < 8; ni++)
#pragma unroll
            for (int r = 0; r < 4; r++) acc[mi][ni][r] = 0.f;

    // Prologue: both stages
    load_stage(0, 0); CP_COMMIT();
    load_stage(1, 1); CP_COMMIT();

    for (int i = 0; i < KT; i++) {
        const int s = i & 1;
        if (i < KT - 1) asm volatile("cp.async.wait_group 1;\n" ::: "memory");
        else            asm volatile("cp.async.wait_group 0;\n" ::: "memory");
        __syncthreads();
        // All warps finished reading buffer s at the barrier of iter i-1...(2-stage:
        // buffer s was last consumed in iter i-2; the barrier above orders it.)
        if (i + 2 < KT + 1 && i + 2 <= KT - 1 + 1) { /* no-op shape keeper */ }
        if (i + 2 - 1 < KT) {           // issue loads for k-tile i+2 into buffer s
            // NOTE: buffer s is consumed THIS iteration; we must load i+2 only
            // after computing. But cp.async here would race. Instead we load
            // into buffer s AFTER compute below.
        }

        const __half* As = reinterpret_cast<const __half*>(dynsmem + s * STAGE_BYTES);
        const __half* Bs = As + BM * SSTR;

#pragma unroll
        for (int ks = 0; ks < 4; ks++) {
            const int kofs = ks * 16 + (lane >> 4) * 8;

            uint32_t af[2][4];
#pragma unroll
            for (int mi = 0; mi < 2; mi++) {
                int row = wm * 32 + mi * 16 + (lane & 15);
                ldmatrix_x4(af[mi][0], af[mi][1], af[mi][2], af[mi][3],
                            &As[row * SSTR + kofs]);
            }

            uint32_t bf[8][2];
#pragma unroll
            for (int ng = 0; ng < 4; ng++) {
                int nrow = wn * 64 + ng * 16 + (lane & 15);
                uint32_t r0, r1, r2, r3;
                ldmatrix_x4(r0, r1, r2, r3, &Bs[nrow * SSTR + kofs]);
                bf[ng * 2 + 0][0] = r0; bf[ng * 2 + 0][1] = r2;
                bf[ng * 2 + 1][0] = r1; bf[ng * 2 + 1][1] = r3;
            }

#pragma unroll
            for (int mi = 0; mi < 2; mi++)
#pragma unroll
                for (int ni = 0; ni < 8; ni++)
                    mma_16816(acc[mi][ni], af[mi], bf[ni]);
        }

        // Refill buffer s with k-tile i+2 (safe: all warps are past the barrier
        // of THIS iteration only after next iter's sync; but within this CTA,
        // each warp has finished ITS OWN reads of buffer s above, and the next
        // consumer of buffer s waits on group completion + barrier at iter i+1.
        __syncthreads();                 // ensure all warps done reading s
        if (i + 2 < KT) {
            load_stage(s, i + 2);
            CP_COMMIT();
        }
    }

    // Epilogue: m16n8 frag: row = lane>>2 (+8 for regs 2,3), col = (lane&3)*2
    const int grow = lane >> 2;
    const int gcol = (lane & 3) * 2;
#pragma unroll
    for (int mi = 0; mi < 2; mi++) {
#pragma unroll
        for (int ni = 0; ni < 8; ni++) {
            int row = bm * BM + wm * 32 + mi * 16 + grow;
            int col = bn * BN + wn * 64 + ni * 8 + gcol;
            float b0 = __ldg(&bias[col]);
            float b1 = __ldg(&bias[col + 1]);
            float2 v0 = make_float2(acc[mi][ni][0] + b0, acc[mi][ni][1] + b1);
            float2 v1 = make_float2(acc[mi][ni][2] + b0, acc[mi][ni][3] + b1);
            *reinterpret_cast<float2*>(&out[(size_t)row * NDIM + col]) = v0;
            *reinterpret_cast<float2*>(&out[(size_t)(row + 8) * NDIM + col]) = v1;
        }
    }
}

// ---------------------------------------------------------------------------
// Launch
// ---------------------------------------------------------------------------
extern "C" void kernel_launch(void* const* d_in, const int* in_sizes, int n_in,
                              void* d_out, int out_size) {
    const float* x    = (const float*)d_in[0];
    const float* w    = (const float*)d_in[1];
    const float* bias = (const float*)d_in[2];
    float* out        = (float*)d_out;

    {
        int n = NW + NX;
        prep_kernel<<<(n + 255) / 256, 256>>>(w, x);
    }
    {
        cudaFuncSetAttribute(gemm_kernel,
                             cudaFuncAttributeMaxDynamicSharedMemorySize, SMEM_BYTES);
        dim3 grid(NDIM / BN, MDIM / BM);   // (16, 64)
        gemm_kernel<<<grid, 256, SMEM_BYTES>>>(bias, out);
    }
}